// round 17
// baseline (speedup 1.0000x reference)
#include <cuda_runtime.h>
#include <stdint.h>
#include <math.h>

// Problem shape (fixed by dataset): B=8, S=2048, H=2048
#define M_DIM 16384
#define H_DIM 2048

// Static device scratch (allowed; no runtime allocation)
__device__ float g_xr[(size_t)M_DIM * H_DIM];    // rna(x)         [m][h]
__device__ float g_xt[(size_t)H_DIM * M_DIM];    // rna(x)^T       [h][m]
__device__ float g_wsum[(size_t)H_DIM * H_DIM];  // rna(Wf + Wp)   [n][k]
__device__ float g_gp[4][(size_t)H_DIM * H_DIM]; // Gram split-K partials
__device__ float g_gram[(size_t)H_DIM * H_DIM];  // rna(x^T x), full (mirrored)
__device__ float g_colsum[H_DIM];                // sum_m x[m][h]
__device__ float g_partials[256];
__device__ float g_scale;

// ---------------------------------------------------------------------------
// helpers
// ---------------------------------------------------------------------------
__device__ __forceinline__ uint32_t smem_u32(const void* p) {
    uint32_t a;
    asm("{ .reg .u64 t; cvta.to.shared.u64 t, %1; cvt.u32.u64 %0, t; }" : "=r"(a) : "l"(p));
    return a;
}
__device__ __forceinline__ uint32_t f2tf32(float f) {
    uint32_t r;
    asm("cvt.rna.tf32.f32 %0, %1;" : "=r"(r) : "f"(f));
    return r;
}
__device__ __forceinline__ uint4 tf32x4(float4 v) {
    uint4 r;
    r.x = f2tf32(v.x); r.y = f2tf32(v.y); r.z = f2tf32(v.z); r.w = f2tf32(v.w);
    return r;
}
__device__ __forceinline__ void cp16(uint32_t s, const void* g) {
    asm volatile("cp.async.cg.shared.global [%0], [%1], 16;" :: "r"(s), "l"(g) : "memory");
}
#define CP_COMMIT() asm volatile("cp.async.commit_group;" ::: "memory")
#define CP_WAIT2()  asm volatile("cp.async.wait_group 2;" ::: "memory")

__device__ __forceinline__ void ldsm4(uint32_t* r, uint32_t addr) {
    asm volatile("ldmatrix.sync.aligned.m8n8.x4.shared.b16 {%0,%1,%2,%3}, [%4];"
                 : "=r"(r[0]), "=r"(r[1]), "=r"(r[2]), "=r"(r[3]) : "r"(addr));
}

#define MMA_TF32(d, a0, a1, a2, a3, b0, b1)                                   \
    asm volatile(                                                             \
        "mma.sync.aligned.m16n8k8.row.col.f32.tf32.tf32.f32 "                 \
        "{%0,%1,%2,%3}, {%4,%5,%6,%7}, {%8,%9}, {%0,%1,%2,%3};\n"             \
        : "+f"((d)[0]), "+f"((d)[1]), "+f"((d)[2]), "+f"((d)[3])              \
        : "r"(a0), "r"(a1), "r"(a2), "r"(a3), "r"(b0), "r"(b1))

// Stage layout (BK=16, CTA tile 256m x 128n):
//   A at +0:     4 k-quad regions of 4KB (256 rows x 16B); row r of quad q at
//                q*4096 + ((r ^ 2q)*16)
//   B at +16384: 4 k-quad regions of 2KB (128 rows x 16B); same XOR scheme
#define STAGE_BYTES 24576
#define NSTAGE 4
#define B_OFF 16384u
#define SMEM_GEMM (NSTAGE * STAGE_BYTES)   // 98304

// ---------------------------------------------------------------------------
// prep kernels
// ---------------------------------------------------------------------------
__global__ __launch_bounds__(256) void prep_w(const float* __restrict__ wf,
                                              const float* __restrict__ wpl) {
    int i4 = blockIdx.x * 256 + threadIdx.x;
    float4 a = ((const float4*)wf)[i4];
    float4 b = ((const float4*)wpl)[i4];
    float4 s = make_float4(a.x + b.x, a.y + b.y, a.z + b.z, a.w + b.w);
    ((uint4*)g_wsum)[i4] = tf32x4(s);
}

__global__ void zero_colsum() {
    g_colsum[blockIdx.x * 1024 + threadIdx.x] = 0.0f;
}

// 32x32 tiles: write rna(x), rna(x)^T, fused column sums
__global__ __launch_bounds__(256) void prep_x(const float* __restrict__ x) {
    __shared__ float tsm[32][33];
    __shared__ float red[8][32];
    const int tx = threadIdx.x, ty = threadIdx.y;
    const int p0 = blockIdx.x * 32, m0 = blockIdx.y * 32;
#pragma unroll
    for (int i = 0; i < 4; i++) {
        const int m = m0 + ty + i * 8;
        float v = x[(size_t)m * H_DIM + p0 + tx];
        float r = __uint_as_float(f2tf32(v));
        g_xr[(size_t)m * H_DIM + p0 + tx] = r;
        tsm[ty + i * 8][tx] = r;
    }
    __syncthreads();
#pragma unroll
    for (int i = 0; i < 4; i++) {
        const int p = p0 + ty + i * 8;
        g_xt[(size_t)p * M_DIM + m0 + tx] = tsm[tx][ty + i * 8];
    }
    {
        float s = tsm[ty][tx] + tsm[ty + 8][tx] + tsm[ty + 16][tx] + tsm[ty + 24][tx];
        red[ty][tx] = s;
    }
    __syncthreads();
    if (ty == 0) {
        float s = 0.0f;
#pragma unroll
        for (int r = 0; r < 8; r++) s += red[r][tx];
        atomicAdd(&g_colsum[p0 + tx], s);
    }
}

// ---------------------------------------------------------------------------
// core mainloop pieces: 8 warps as 4(m) x 2(n), 64x64 warp tiles
// ---------------------------------------------------------------------------
struct Frags {
    uint32_t rowA16[4];   // (wm + mi*16 + (lane&15)) * 16
    uint32_t rowB16[4];   // (wn + (2P + (G>>1))*8 + (lane&7)) * 16
    uint32_t qa, qb;
};

__device__ __forceinline__ void init_frags(Frags& F, int lane, int wm, int wn) {
    const int G = lane >> 3;
#pragma unroll
    for (int mi = 0; mi < 4; mi++)
        F.rowA16[mi] = (uint32_t)(wm + mi * 16 + (lane & 15)) * 16u;
#pragma unroll
    for (int P = 0; P < 4; P++)
        F.rowB16[P] = (uint32_t)(wn + (2 * P + (G >> 1)) * 8 + (lane & 7)) * 16u;
    F.qa = (uint32_t)(lane >> 4);
    F.qb = (uint32_t)(G & 1);
}

__device__ __forceinline__ void compute_stage(const Frags& F, uint32_t stg,
                                              float acc[4][8][4]) {
#pragma unroll
    for (int ks8 = 0; ks8 < 2; ks8++) {
        const uint32_t aq = (uint32_t)(ks8 * 2) + F.qa;
        const uint32_t bq = (uint32_t)(ks8 * 2) + F.qb;
        uint32_t af[4][4], bf[4][4];
#pragma unroll
        for (int mi = 0; mi < 4; mi++)
            ldsm4(af[mi], stg + aq * 4096u + (F.rowA16[mi] ^ (aq << 5)));
#pragma unroll
        for (int P = 0; P < 4; P++)
            ldsm4(bf[P], stg + B_OFF + bq * 2048u + (F.rowB16[P] ^ (bq << 5)));
#pragma unroll
        for (int mi = 0; mi < 4; mi++)
#pragma unroll
            for (int P = 0; P < 4; P++) {
                MMA_TF32(acc[mi][2 * P],     af[mi][0], af[mi][1], af[mi][2], af[mi][3],
                         bf[P][0], bf[P][1]);
                MMA_TF32(acc[mi][2 * P + 1], af[mi][0], af[mi][1], af[mi][2], af[mi][3],
                         bf[P][2], bf[P][3]);
            }
    }
}

// Loader: lq = tid&3 (k-quad), lr = tid>>2 (0..63).
// A rows lr, lr+64, lr+128, lr+192 (offsets +0,+1024,+2048,+3072 — XOR only
// touches row bits 1-2, so +64 rows = +1024B exactly). B rows lr, lr+64.
#define ISSUE_STAGE(kt, gA, gB, ldgA, ldgB, sA, sB)  do {                  \
        const uint32_t st_ = (uint32_t)((kt) & (NSTAGE - 1)) * STAGE_BYTES; \
        const size_t ko_ = (size_t)(kt) * 16;                              \
        cp16((sA) + st_,          (gA) + ko_);                             \
        cp16((sA) + st_ + 1024u,  (gA) + ko_ + (size_t)64  * (ldgA));      \
        cp16((sA) + st_ + 2048u,  (gA) + ko_ + (size_t)128 * (ldgA));      \
        cp16((sA) + st_ + 3072u,  (gA) + ko_ + (size_t)192 * (ldgA));      \
        cp16((sB) + st_,          (gB) + ko_);                             \
        cp16((sB) + st_ + 1024u,  (gB) + ko_ + (size_t)64  * (ldgB));      \
    } while (0)

#define MAINLOOP(KT, gA, gB, ldgA, ldgB, sA, sB, sbase, F, acc)  do {      \
        ISSUE_STAGE(0, gA, gB, ldgA, ldgB, sA, sB); CP_COMMIT();           \
        ISSUE_STAGE(1, gA, gB, ldgA, ldgB, sA, sB); CP_COMMIT();           \
        ISSUE_STAGE(2, gA, gB, ldgA, ldgB, sA, sB); CP_COMMIT();           \
        for (int kt = 0; kt < (KT); kt++) {                                \
            CP_WAIT2();                                                    \
            __syncthreads();                                               \
            if (kt + 3 < (KT)) { ISSUE_STAGE(kt + 3, gA, gB, ldgA, ldgB, sA, sB); } \
            CP_COMMIT();                                                   \
            compute_stage(F, (sbase) + (uint32_t)(kt & (NSTAGE - 1)) * STAGE_BYTES, acc); \
        }                                                                  \
    } while (0)

#define DECL_ACC(acc)                                                      \
    float acc[4][8][4];                                                    \
    _Pragma("unroll")                                                      \
    for (int mi = 0; mi < 4; mi++)                                         \
        _Pragma("unroll")                                                  \
        for (int ni = 0; ni < 8; ni++)                                     \
            _Pragma("unroll")                                              \
            for (int c = 0; c < 4; c++) acc[mi][ni][c] = 0.0f;

// ---------------------------------------------------------------------------
// GEMM1: combined[m,n] = g_xr[m,:] . g_wsum[n,:] + bias[n]   (tile 256m x 128n)
// ---------------------------------------------------------------------------
__global__ __launch_bounds__(256, 1) void gemm1_k(
    const float* __restrict__ bias, float* __restrict__ C)
{
    extern __shared__ char sm[];
    const uint32_t sbase = smem_u32(sm);
    const int tid = threadIdx.x, lane = tid & 31, warp = tid >> 5;
    const int g = lane >> 2, t = lane & 3;
    const int wm = (warp >> 1) * 64, wn = (warp & 1) * 64;
    const int m0 = blockIdx.y * 256, n0 = blockIdx.x * 128;

    const int lq = tid & 3, lr = tid >> 2;
    const float* gA = g_xr   + (size_t)(m0 + lr) * H_DIM + lq * 4;
    const float* gB = g_wsum + (size_t)(n0 + lr) * H_DIM + lq * 4;
    const uint32_t sA = sbase + (uint32_t)lq * 4096u + (uint32_t)((lr ^ (2 * lq)) * 16);
    const uint32_t sB = sbase + B_OFF + (uint32_t)lq * 2048u + (uint32_t)((lr ^ (2 * lq)) * 16);

    Frags F;
    init_frags(F, lane, wm, wn);
    DECL_ACC(acc)

    MAINLOOP(H_DIM / 16, gA, gB, H_DIM, H_DIM, sA, sB, sbase, F, acc);

#pragma unroll
    for (int ni = 0; ni < 8; ni++) {
        const int n = wn + ni * 8 + 2 * t;
        const float2 bv = *(const float2*)&bias[n0 + n];
#pragma unroll
        for (int mi = 0; mi < 4; mi++) {
            const int m = wm + mi * 16 + g;
            *(float2*)&C[(size_t)(m0 + m) * H_DIM + n0 + n] =
                make_float2(acc[mi][ni][0] + bv.x, acc[mi][ni][1] + bv.y);
            *(float2*)&C[(size_t)(m0 + m + 8) * H_DIM + n0 + n] =
                make_float2(acc[mi][ni][2] + bv.x, acc[mi][ni][3] + bv.y);
        }
    }
}

// ---------------------------------------------------------------------------
// Gram (split-K=4, lower-triangle 256x128 tiles):
//   g_gp[sp][p,q] = sum_{m in split} xt[p,m]*xt[q,m]
// Tiles (bp, bq) with bq <= 2*bp+1; cum(bp) = bp*(bp+1); 72 tiles total.
// ---------------------------------------------------------------------------
__global__ __launch_bounds__(256, 1) void gram_k()
{
    extern __shared__ char sm[];
    const uint32_t sbase = smem_u32(sm);
    const int tid = threadIdx.x, lane = tid & 31, warp = tid >> 5;
    const int g = lane >> 2, t = lane & 3;
    const int wm = (warp >> 1) * 64, wn = (warp & 1) * 64;

    const int tt = blockIdx.x;
    int bp = (int)((sqrtf(4.0f * (float)tt + 1.0f) - 1.0f) * 0.5f);
    while ((bp + 1) * (bp + 2) <= tt) bp++;
    while (bp * (bp + 1) > tt) bp--;
    const int bq = tt - bp * (bp + 1);

    const int p0 = bp * 256, q0 = bq * 128;
    const int sp = blockIdx.y;
    const int mbase = sp * (M_DIM / 4);

    const int lq = tid & 3, lr = tid >> 2;
    const float* gA = g_xt + (size_t)(p0 + lr) * M_DIM + mbase + lq * 4;
    const float* gB = g_xt + (size_t)(q0 + lr) * M_DIM + mbase + lq * 4;
    const uint32_t sA = sbase + (uint32_t)lq * 4096u + (uint32_t)((lr ^ (2 * lq)) * 16);
    const uint32_t sB = sbase + B_OFF + (uint32_t)lq * 2048u + (uint32_t)((lr ^ (2 * lq)) * 16);

    Frags F;
    init_frags(F, lane, wm, wn);
    DECL_ACC(acc)

    MAINLOOP((M_DIM / 4) / 16, gA, gB, M_DIM, M_DIM, sA, sB, sbase, F, acc);

    float* dst = g_gp[sp];
#pragma unroll
    for (int ni = 0; ni < 8; ni++) {
        const int q = q0 + wn + ni * 8 + 2 * t;
#pragma unroll
        for (int mi = 0; mi < 4; mi++) {
            const int p = p0 + wm + mi * 16 + g;
            *(float2*)&dst[(size_t)p * H_DIM + q]       = make_float2(acc[mi][ni][0], acc[mi][ni][1]);
            *(float2*)&dst[(size_t)(p + 8) * H_DIM + q] = make_float2(acc[mi][ni][2], acc[mi][ni][3]);
        }
    }
}

// ---------------------------------------------------------------------------
// Mirror: g_gram[i][j] = g_gram[j][i] = rna(sum_sp g_gp[sp][i][j])  for i >= j
// ---------------------------------------------------------------------------
__global__ __launch_bounds__(128) void mirror_k() {
    const int i = blockIdx.y;
    const int j = blockIdx.x * 128 + threadIdx.x;
    if (j > i) return;
    const size_t idx = (size_t)i * H_DIM + j;
    float s = 0.0f;
#pragma unroll
    for (int sp = 0; sp < 4; sp++) s += g_gp[sp][idx];
    const float r = __uint_as_float(f2tf32(s));
    g_gram[idx] = r;
    g_gram[(size_t)j * H_DIM + i] = r;
}

// ---------------------------------------------------------------------------
// hebb GEMM + fused output (tile 256p x 128q):
//   outw[p,q] = wp[p,q] + f*(G[p,:].wsum[q,:] + colsum[p]*b[q]); ssq partials.
// ---------------------------------------------------------------------------
__global__ __launch_bounds__(256, 1) void hebb_k(
    const float* __restrict__ wpl, const float* __restrict__ pr,
    const float* __restrict__ hs, const float* __restrict__ bias,
    float* __restrict__ outw)
{
    extern __shared__ char sm[];
    __shared__ float red[8];
    const uint32_t sbase = smem_u32(sm);
    const int tid = threadIdx.x, lane = tid & 31, warp = tid >> 5;
    const int g = lane >> 2, t = lane & 3;
    const int wm = (warp >> 1) * 64, wn = (warp & 1) * 64;
    const int p0 = blockIdx.y * 256, q0 = blockIdx.x * 128;

    const int lq = tid & 3, lr = tid >> 2;
    const float* gA = g_gram + (size_t)(p0 + lr) * H_DIM + lq * 4;
    const float* gB = g_wsum + (size_t)(q0 + lr) * H_DIM + lq * 4;
    const uint32_t sA = sbase + (uint32_t)lq * 4096u + (uint32_t)((lr ^ (2 * lq)) * 16);
    const uint32_t sB = sbase + B_OFF + (uint32_t)lq * 2048u + (uint32_t)((lr ^ (2 * lq)) * 16);

    Frags F;
    init_frags(F, lane, wm, wn);
    DECL_ACC(acc)

    MAINLOOP(H_DIM / 16, gA, gB, H_DIM, H_DIM, sA, sB, sbase, F, acc);

    const float f = pr[0] * hs[0] * (1.0f / (float)M_DIM);
    float ssq = 0.0f;
#pragma unroll
    for (int ni = 0; ni < 8; ni++) {
        const int q = q0 + wn + ni * 8 + 2 * t;
        const float2 bv = *(const float2*)&bias[q];
#pragma unroll
        for (int mi = 0; mi < 4; mi++) {
            const int p = p0 + wm + mi * 16 + g;
            const float cs0 = g_colsum[p], cs1 = g_colsum[p + 8];
            {
                float2 w = *(const float2*)&wpl[(size_t)p * H_DIM + q];
                float2 v = make_float2(w.x + f * (acc[mi][ni][0] + cs0 * bv.x),
                                       w.y + f * (acc[mi][ni][1] + cs0 * bv.y));
                *(float2*)&outw[(size_t)p * H_DIM + q] = v;
                ssq += v.x * v.x + v.y * v.y;
            }
            {
                float2 w = *(const float2*)&wpl[(size_t)(p + 8) * H_DIM + q];
                float2 v = make_float2(w.x + f * (acc[mi][ni][2] + cs1 * bv.x),
                                       w.y + f * (acc[mi][ni][3] + cs1 * bv.y));
                *(float2*)&outw[(size_t)(p + 8) * H_DIM + q] = v;
                ssq += v.x * v.x + v.y * v.y;
            }
        }
    }

#pragma unroll
    for (int o = 16; o; o >>= 1) ssq += __shfl_xor_sync(0xffffffffu, ssq, o);
    if (lane == 0) red[warp] = ssq;
    __syncthreads();
    if (tid == 0) {
        float s = 0.0f;
#pragma unroll
        for (int w = 0; w < 8; w++) s += red[w];
        g_partials[blockIdx.y * gridDim.x + blockIdx.x] = s;  // 0..127
    }
}

// ---------------------------------------------------------------------------
// Frobenius norm finalize + conditional scale
// (g_partials[128..255] are never written: zero-initialized device globals)
// ---------------------------------------------------------------------------
__global__ void finalize_kernel() {
    const int tid = threadIdx.x;
    __shared__ float red[8];
    float v = g_partials[tid];
#pragma unroll
    for (int o = 16; o; o >>= 1) v += __shfl_xor_sync(0xffffffffu, v, o);
    if ((tid & 31) == 0) red[tid >> 5] = v;
    __syncthreads();
    if (tid == 0) {
        float s = 0.0f;
#pragma unroll
        for (int w = 0; w < 8; w++) s += red[w];
        const float n = sqrtf(s);
        g_scale = (n > 1.0f) ? (1.0f / n) : 1.0f;
    }
}

__global__ void scale_kernel(float* __restrict__ w) {
    const float s = g_scale;
    const int n4 = (H_DIM * H_DIM) / 4;
    float4* w4 = (float4*)w;
    for (int i = blockIdx.x * blockDim.x + threadIdx.x; i < n4;
         i += gridDim.x * blockDim.x) {
        float4 v = w4[i];
        v.x *= s; v.y *= s; v.z *= s; v.w *= s;
        w4[i] = v;
    }
}

// ---------------------------------------------------------------------------
// Inputs: x, plastic_weights, plasticity_rate, fixed_w, fixed_b, hebbian_strength
// Output: combined [16384,2048] ++ new_w [2048,2048]
// ---------------------------------------------------------------------------
extern "C" void kernel_launch(void* const* d_in, const int* in_sizes, int n_in,
                              void* d_out, int out_size)
{
    const float* x  = (const float*)d_in[0];
    const float* wp = (const float*)d_in[1];
    const float* pr = (const float*)d_in[2];
    const float* wf = (const float*)d_in[3];
    const float* fb = (const float*)d_in[4];
    const float* hs = (const float*)d_in[5];

    float* combined = (float*)d_out;
    float* outw     = combined + (size_t)M_DIM * H_DIM;

    cudaFuncSetAttribute(gemm1_k, cudaFuncAttributeMaxDynamicSharedMemorySize, SMEM_GEMM);
    cudaFuncSetAttribute(gram_k,  cudaFuncAttributeMaxDynamicSharedMemorySize, SMEM_GEMM);
    cudaFuncSetAttribute(hebb_k,  cudaFuncAttributeMaxDynamicSharedMemorySize, SMEM_GEMM);

    prep_w<<<4096, 256>>>(wf, wp);
    zero_colsum<<<2, 1024>>>();
    prep_x<<<dim3(H_DIM / 32, M_DIM / 32), dim3(32, 8)>>>(x);

    gram_k<<<dim3(72, 4), 256, SMEM_GEMM>>>();
    gemm1_k<<<dim3(16, 64), 256, SMEM_GEMM>>>(fb, combined);
    mirror_k<<<dim3(16, 2048), 128>>>();
    hebb_k<<<dim3(16, 8), 256, SMEM_GEMM>>>(wp, pr, hs, fb, outw);

    finalize_kernel<<<1, 256>>>();
    scale_kernel<<<2048, 256>>>(outw);
}